// round 14
// baseline (speedup 1.0000x reference)
#include <cuda_runtime.h>
#include <cuda_fp16.h>
#include <cstdint>
#include <cstddef>

#define B_DIM 8192
#define HIN   4096
#define HOUT  4096
#define KE    4160          // 4096 + 32 LoRA + 32 zero pad = 65 chunks of K=64

// ---------------- device scratch ----------------
__device__ __align__(16) __half g_xp[(size_t)B_DIM * KE];
__device__ __align__(16) __half g_wp[(size_t)HOUT * KE];
__device__ __align__(16) __half g_qa16[32 * HIN];

// ---------------- helpers ----------------
__device__ __forceinline__ uint32_t smem_u32(const void* p) {
    uint32_t a;
    asm("{ .reg .u64 t; cvta.to.shared.u64 t, %1; cvt.u32.u64 %0, t; }" : "=r"(a) : "l"(p));
    return a;
}

__device__ __forceinline__ uint2 pack4h(float4 f) {
    __half2 a = __floats2half2_rn(f.x, f.y);
    __half2 b = __floats2half2_rn(f.z, f.w);
    uint2 r;
    r.x = *reinterpret_cast<uint32_t*>(&a);
    r.y = *reinterpret_cast<uint32_t*>(&b);
    return r;
}

__device__ __forceinline__ void cpa16(uint32_t dst, const void* src) {
    asm volatile("cp.async.cg.shared.global [%0], [%1], 16;" :: "r"(dst), "l"(src));
}

__device__ __forceinline__ void ldm4(uint32_t* r, uint32_t addr) {
    asm volatile("ldmatrix.sync.aligned.m8n8.x4.shared.b16 {%0,%1,%2,%3}, [%4];"
                 : "=r"(r[0]), "=r"(r[1]), "=r"(r[2]), "=r"(r[3]) : "r"(addr));
}

__device__ __forceinline__ void ldm2(uint32_t* r, uint32_t addr) {
    asm volatile("ldmatrix.sync.aligned.m8n8.x2.shared.b16 {%0,%1}, [%2];"
                 : "=r"(r[0]), "=r"(r[1]) : "r"(addr));
}

__device__ __forceinline__ void mma16816(float* c, const uint32_t* a, uint32_t b0, uint32_t b1) {
    asm volatile(
        "mma.sync.aligned.m16n8k16.row.col.f32.f16.f16.f32 "
        "{%0,%1,%2,%3}, {%4,%5,%6,%7}, {%8,%9}, {%0,%1,%2,%3};"
        : "+f"(c[0]), "+f"(c[1]), "+f"(c[2]), "+f"(c[3])
        : "r"(a[0]), "r"(a[1]), "r"(a[2]), "r"(a[3]), "r"(b0), "r"(b1));
}

// ================= cvt_qa: qa fp32 -> fp16 (tiny) =================
__global__ void __launch_bounds__(256) cvt_qa_kernel(const float* __restrict__ qa)
{
    const int kr = blockIdx.x, tid = threadIdx.x;
    #pragma unroll
    for (int i = 0; i < 4; i++) {
        int c4 = (tid + i * 256) << 2;
        float4 f = *reinterpret_cast<const float4*>(qa + (size_t)kr * HIN + c4);
        *reinterpret_cast<uint2*>(g_qa16 + (size_t)kr * HIN + c4) = pack4h(f);
    }
}

// ================= Fused prep kernel =================
// Blocks [0,256):   LoRA+x-convert, 32 x-rows, K-chunks of 128 (32 iterations).
// Blocks [256,768): W->fp16 conversion (8 rows, warp-per-row) + scaling*qb cols + pad.
#define NLORA_BLK 256
// LoRA smem: XA0@0 XA1@8192 QB0@16384 QB1@24576 QB2@32768 (40KB), 256B row pitch
#define PXA(s) ((uint32_t)(s) * 8192u)
#define PQB(q) (16384u + (uint32_t)(q) * 8192u)
#define LNCH   32

__global__ void __launch_bounds__(256) prep_kernel(
    const float* __restrict__ x, const float* __restrict__ tkw,
    const float* __restrict__ W, const float* __restrict__ qb,
    const float* __restrict__ scaling)
{
    const int tid  = threadIdx.x;
    const int lane = tid & 31, w = tid >> 5;

    if (blockIdx.x < NLORA_BLK) {
        __shared__ __align__(128) char smem[5 * 8192];
        const int b0 = blockIdx.x * 32;
        const int lid = lane, wid = w;
        const int mt = wid & 1, nt = wid >> 1;
        const int lr = lid & 15;
        const uint32_t lhb = (uint32_t)(lid >> 4) * 16u;
        const uint32_t sbase = smem_u32(smem);

        // x loader: thread -> col8 = (tid&15)*8 (8 fp32 -> 1 uint4 fp16), rows tid>>4, +16
        const int xc8 = (tid & 15) * 8;
        const int xr0 = tid >> 4, xr1 = xr0 + 16;
        const uint32_t xd0 = (uint32_t)xr0 * 256u + (((uint32_t)xc8 * 2u) ^ ((uint32_t)(xr0 & 7) << 4));
        const uint32_t xd1 = (uint32_t)xr1 * 256u + (((uint32_t)xc8 * 2u) ^ ((uint32_t)(xr1 & 7) << 4));
        // qa loader: thread -> row qr = tid>>3, segments qs and qs+8
        const int qr = tid >> 3, qs = tid & 7;
        const uint32_t qrx = ((uint32_t)(qr & 7) << 4);
        const uint32_t qd0 = (uint32_t)qr * 256u + (((uint32_t)qs * 16u) ^ qrx);
        const uint32_t qd1 = (uint32_t)qr * 256u + (((uint32_t)(qs + 8) * 16u) ^ qrx);

        // mma addressing (row pitch 256B)
        const uint32_t arow = (uint32_t)(mt * 16 + lr);
        const uint32_t abase = arow * 256u, arx = (arow & 7u) << 4;
        const uint32_t brow = (uint32_t)(nt * 8 + (lid & 7));
        const uint32_t bbase = brow * 256u, brx = (brow & 7u) << 4;
        const uint32_t bhalf = ((uint32_t)(lid >> 3) & 1u) * 16u;

        float c[4] = {0.f, 0.f, 0.f, 0.f};
        float4 f00, f01, f10, f11;   // chunk prefetch regs: rows (xr0,xr1) x col halves

        const float* xb0 = x + (size_t)(b0 + xr0) * HIN;
        const float* xb1 = x + (size_t)(b0 + xr1) * HIN;

        // prologue: x[0] -> regs -> convert into XA0 + g_xp; qa[0], qa[1] in flight
        f00 = *reinterpret_cast<const float4*>(xb0 + xc8);
        f01 = *reinterpret_cast<const float4*>(xb0 + xc8 + 4);
        f10 = *reinterpret_cast<const float4*>(xb1 + xc8);
        f11 = *reinterpret_cast<const float4*>(xb1 + xc8 + 4);
        cpa16(sbase + PQB(0) + qd0, g_qa16 + (size_t)qr * HIN + qs * 8);
        cpa16(sbase + PQB(0) + qd1, g_qa16 + (size_t)qr * HIN + 64 + qs * 8);
        asm volatile("cp.async.commit_group;" ::: "memory");
        {
            uint2 a0 = pack4h(f00), a1 = pack4h(f01);
            uint2 b0v = pack4h(f10), b1v = pack4h(f11);
            *reinterpret_cast<uint4*>(smem + PXA(0) + xd0) = make_uint4(a0.x, a0.y, a1.x, a1.y);
            *reinterpret_cast<uint4*>(smem + PXA(0) + xd1) = make_uint4(b0v.x, b0v.y, b1v.x, b1v.y);
            *reinterpret_cast<uint4*>(g_xp + (size_t)(b0 + xr0) * KE + xc8) = make_uint4(a0.x, a0.y, a1.x, a1.y);
            *reinterpret_cast<uint4*>(g_xp + (size_t)(b0 + xr1) * KE + xc8) = make_uint4(b0v.x, b0v.y, b1v.x, b1v.y);
        }
        f00 = *reinterpret_cast<const float4*>(xb0 + 128 + xc8);
        f01 = *reinterpret_cast<const float4*>(xb0 + 128 + xc8 + 4);
        f10 = *reinterpret_cast<const float4*>(xb1 + 128 + xc8);
        f11 = *reinterpret_cast<const float4*>(xb1 + 128 + xc8 + 4);
        cpa16(sbase + PQB(1) + qd0, g_qa16 + (size_t)qr * HIN + 128 + qs * 8);
        cpa16(sbase + PQB(1) + qd1, g_qa16 + (size_t)qr * HIN + 128 + 64 + qs * 8);
        asm volatile("cp.async.commit_group;" ::: "memory");

        for (int ch = 0; ch < LNCH; ch++) {
            const int s = ch & 1;
            const int q = ch % 3;
            asm volatile("cp.async.wait_group 1;" ::: "memory");
            __syncthreads();
            if (ch + 1 < LNCH) {                 // convert x[ch+1] -> XA[1-s] + g_xp
                const int k1 = (ch + 1) * 128;
                uint2 a0 = pack4h(f00), a1 = pack4h(f01);
                uint2 b0v = pack4h(f10), b1v = pack4h(f11);
                *reinterpret_cast<uint4*>(smem + PXA(1 - s) + xd0) = make_uint4(a0.x, a0.y, a1.x, a1.y);
                *reinterpret_cast<uint4*>(smem + PXA(1 - s) + xd1) = make_uint4(b0v.x, b0v.y, b1v.x, b1v.y);
                *reinterpret_cast<uint4*>(g_xp + (size_t)(b0 + xr0) * KE + k1 + xc8) = make_uint4(a0.x, a0.y, a1.x, a1.y);
                *reinterpret_cast<uint4*>(g_xp + (size_t)(b0 + xr1) * KE + k1 + xc8) = make_uint4(b0v.x, b0v.y, b1v.x, b1v.y);
            }
            if (ch + 2 < LNCH) {                 // prefetch x[ch+2] regs + qa[ch+2] cpa
                const int k2 = (ch + 2) * 128;
                f00 = *reinterpret_cast<const float4*>(xb0 + k2 + xc8);
                f01 = *reinterpret_cast<const float4*>(xb0 + k2 + xc8 + 4);
                f10 = *reinterpret_cast<const float4*>(xb1 + k2 + xc8);
                f11 = *reinterpret_cast<const float4*>(xb1 + k2 + xc8 + 4);
                cpa16(sbase + PQB((ch + 2) % 3) + qd0, g_qa16 + (size_t)qr * HIN + k2 + qs * 8);
                cpa16(sbase + PQB((ch + 2) % 3) + qd1, g_qa16 + (size_t)qr * HIN + k2 + 64 + qs * 8);
            }
            asm volatile("cp.async.commit_group;" ::: "memory");

            #pragma unroll
            for (int ks = 0; ks < 8; ks++) {     // 8 k16 steps per K=128 chunk
                const uint32_t kb = (uint32_t)ks * 32u;
                uint32_t a[4], b[2];
                ldm4(a, sbase + PXA(s) + abase + ((kb + lhb) ^ arx));
                ldm2(b, sbase + PQB(q) + bbase + ((kb + bhalf) ^ brx));
                mma16816(c, a, b[0], b[1]);
            }
        }

        // epilogue: aw * tkw -> x-plane cols [4096,4128), fp16
        int m0r = b0 + mt * 16 + (lid >> 2);
        int col = nt * 8 + (lid & 3) * 2;
        float t0 = tkw[m0r * 4 + nt];
        float t1 = tkw[(m0r + 8) * 4 + nt];
        __half* p0 = g_xp + (size_t)m0r * KE + 4096 + col;
        __half* p1 = g_xp + (size_t)(m0r + 8) * KE + 4096 + col;
        p0[0] = __float2half(c[0] * t0);
        p0[1] = __float2half(c[1] * t0);
        p1[0] = __float2half(c[2] * t1);
        p1[1] = __float2half(c[3] * t1);
        // zero pad cols [4128, 4160): 32 rows x 4 uint2
        if (tid < 128) {
            int r = tid >> 2, seg = tid & 3;
            *reinterpret_cast<uint2*>(g_xp + (size_t)(b0 + r) * KE + 4128 + seg * 8) =
                make_uint2(0u, 0u);
        }
    } else {
        // ---------------- W conversion, 8 rows, warp-per-row ----------------
        const int o0 = (blockIdx.x - NLORA_BLK) * 8;
        const int o  = o0 + w;
        const size_t rb = (size_t)o * KE;
        const float* wr = W + (size_t)o * HIN;
        #pragma unroll 8
        for (int i = 0; i < 32; i++) {
            int c4 = (i * 32 + lane) << 2;
            float4 f = *reinterpret_cast<const float4*>(wr + c4);
            *reinterpret_cast<uint2*>(g_wp + rb + c4) = pack4h(f);
        }
        if (tid < 64) {  // LoRA cols [4096,4128)
            int row = o0 + (tid >> 3), t8 = tid & 7;
            int c4 = 4096 + t8 * 4;
            int kk = t8 >> 1, rr = (t8 & 1) * 4;     // kr = kk*8 + rr..rr+3
            const float* p = qb + ((size_t)kk * HOUT + row) * 8 + rr;
            float sc = scaling[row];
            float4 f = make_float4(p[0] * sc, p[1] * sc, p[2] * sc, p[3] * sc);
            *reinterpret_cast<uint2*>(g_wp + (size_t)row * KE + c4) = pack4h(f);
        } else if (tid < 96) {  // zero pad [4128,4160)
            int row = o0 + ((tid - 64) >> 2), seg = tid & 3;
            *reinterpret_cast<uint2*>(g_wp + (size_t)row * KE + 4128 + seg * 8) =
                make_uint2(0u, 0u);
        }
    }
}

// ================= GEMM: 2 CTAs/SM, 256 threads, tile 128x128, K=64 chunks =============
// 8 warps in 4x2 grid; smem row = 128B; 3-stage ring, wait_group 1.
// Loop order (PROVEN r11/r12): wait_group -> __syncthreads -> issue -> compute.
// NOTE: cp.async wait_group is PER-THREAD; the __syncthreads immediately after the
// wait is what makes other threads' async copies visible. Do not reorder.
#define A_OFF   0
#define W_OFF   16384
#define STAGE_B 32768
#define NSTAGE  3
#define SMEM_TOTAL (NSTAGE * STAGE_B)
#define NCHUNK  65

__device__ __forceinline__ void issue_stage(uint32_t st, int ch, int m0, int n0, int tid)
{
    const int r8 = tid >> 3, sg = tid & 7;
    const size_t kofs = (size_t)ch * 64 + sg * 8;
    const uint32_t sgb = (uint32_t)sg * 16u;
    #pragma unroll
    for (int j = 0; j < 4; j++) {
        int row = r8 + 32 * j;
        uint32_t d = (uint32_t)row * 128u + (sgb ^ ((uint32_t)(row & 7) << 4));
        cpa16(st + A_OFF + d, g_xp + (size_t)(m0 + row) * KE + kofs);
    }
    #pragma unroll
    for (int j = 0; j < 4; j++) {
        int row = r8 + 32 * j;
        uint32_t d = (uint32_t)row * 128u + (sgb ^ ((uint32_t)(row & 7) << 4));
        cpa16(st + W_OFF + d, g_wp + (size_t)(n0 + row) * KE + kofs);
    }
    asm volatile("cp.async.commit_group;" ::: "memory");
}

__global__ void __launch_bounds__(256, 2) fused_gemm_kernel(float* __restrict__ out)
{
    extern __shared__ char smem[];
    const int tid = threadIdx.x;
    const int wid = tid >> 5, lid = tid & 31;
    const int wr = wid >> 1, wc = wid & 1;
    const int n0 = blockIdx.x * 128;
    const int m0 = blockIdx.y * 128;
    const uint32_t sbase = smem_u32(smem);
    const int lr = lid & 15;
    const uint32_t lhb = (uint32_t)(lid >> 4) * 16u;

    uint32_t abase[2], arx[2], bbase[4], brx[4];
    #pragma unroll
    for (int t = 0; t < 2; t++) {
        uint32_t row = (uint32_t)(wr * 32 + t * 16 + lr);
        abase[t] = row * 128u; arx[t] = (row & 7u) << 4;
    }
    #pragma unroll
    for (int g = 0; g < 4; g++) {
        uint32_t row = (uint32_t)(wc * 64 + g * 16 + lr);
        bbase[g] = row * 128u; brx[g] = (row & 7u) << 4;
    }

    float acc[2][8][4];
    #pragma unroll
    for (int t = 0; t < 2; t++)
        #pragma unroll
        for (int j = 0; j < 8; j++)
            #pragma unroll
            for (int e = 0; e < 4; e++) acc[t][j][e] = 0.f;

    issue_stage(sbase + 0 * STAGE_B, 0, m0, n0, tid);
    issue_stage(sbase + 1 * STAGE_B, 1, m0, n0, tid);

    int sidx = 0;
    for (int ch = 0; ch < NCHUNK; ch++) {
        const uint32_t st = sbase + sidx * STAGE_B;
        const uint32_t sa = st + A_OFF, sw = st + W_OFF;

        asm volatile("cp.async.wait_group 1;" ::: "memory");
        __syncthreads();
        if (ch + 2 < NCHUNK) {
            int ps = sidx + 2; if (ps >= NSTAGE) ps -= NSTAGE;
            issue_stage(sbase + ps * STAGE_B, ch + 2, m0, n0, tid);
        } else {
            asm volatile("cp.async.commit_group;" ::: "memory");  // keep group count in step
        }

        #pragma unroll
        for (int ks = 0; ks < 4; ks++) {
            const uint32_t chb = (uint32_t)ks * 32u + lhb;
            uint32_t ah[2][4];
            ldm4(ah[0], sa + abase[0] + (chb ^ arx[0]));
            ldm4(ah[1], sa + abase[1] + (chb ^ arx[1]));

            uint32_t bfrag[2][4];
            ldm4(bfrag[0], sw + bbase[0] + (chb ^ brx[0]));
            #pragma unroll
            for (int g = 0; g < 4; g++) {
                const int cur = g & 1;
                if (g < 3)
                    ldm4(bfrag[cur ^ 1], sw + bbase[g + 1] + (chb ^ brx[g + 1]));
                #pragma unroll
                for (int t = 0; t < 2; t++) {
                    #pragma unroll
                    for (int j2 = 0; j2 < 2; j2++)
                        mma16816(acc[t][g * 2 + j2], ah[t],
                                 bfrag[cur][j2], bfrag[cur][j2 + 2]);
                }
            }
        }
        if (++sidx >= NSTAGE) sidx = 0;
    }

    #pragma unroll
    for (int t = 0; t < 2; t++) {
        int mr = m0 + wr * 32 + t * 16 + (lid >> 2);
        #pragma unroll
        for (int j = 0; j < 8; j++) {
            int col = n0 + wc * 64 + j * 8 + (lid & 3) * 2;
            *reinterpret_cast<float2*>(out + (size_t)mr * HOUT + col) =
                make_float2(acc[t][j][0], acc[t][j][1]);
            *reinterpret_cast<float2*>(out + (size_t)(mr + 8) * HOUT + col) =
                make_float2(acc[t][j][2], acc[t][j][3]);
        }
    }
}

// ================= launch =================
extern "C" void kernel_launch(void* const* d_in, const int* in_sizes, int n_in,
                              void* d_out, int out_size) {
    const float* x       = (const float*)d_in[0];
    const float* tkw     = (const float*)d_in[1];
    const float* W       = (const float*)d_in[2];
    const float* qa      = (const float*)d_in[3];
    const float* qb      = (const float*)d_in[4];
    const float* scaling = (const float*)d_in[5];
    float* out = (float*)d_out;

    cvt_qa_kernel<<<32, 256>>>(qa);
    prep_kernel<<<NLORA_BLK + HOUT / 8, 256>>>(x, tkw, W, qb, scaling);

    cudaFuncSetAttribute(fused_gemm_kernel,
                         cudaFuncAttributeMaxDynamicSharedMemorySize, SMEM_TOTAL);
    dim3 grid(HOUT / 128, B_DIM / 128);
    fused_gemm_kernel<<<grid, 256, SMEM_TOTAL>>>(out);
}

// round 15
// speedup vs baseline: 1.2553x; 1.2553x over previous
#include <cuda_runtime.h>
#include <cuda_fp16.h>
#include <cstdint>
#include <cstddef>

#define B_DIM 8192
#define HIN   4096
#define HOUT  4096
#define KE    4160          // 4096 + 32 LoRA + 32 zero pad = 65 chunks of K=64

// ---------------- device scratch ----------------
__device__ __align__(16) __half g_xp[(size_t)B_DIM * KE];
__device__ __align__(16) __half g_wp[(size_t)HOUT * KE];
__device__ __align__(16) __half g_qa16[32 * HIN];

// ---------------- helpers ----------------
__device__ __forceinline__ uint32_t smem_u32(const void* p) {
    uint32_t a;
    asm("{ .reg .u64 t; cvta.to.shared.u64 t, %1; cvt.u32.u64 %0, t; }" : "=r"(a) : "l"(p));
    return a;
}

__device__ __forceinline__ uint2 pack4h(float4 f) {
    __half2 a = __floats2half2_rn(f.x, f.y);
    __half2 b = __floats2half2_rn(f.z, f.w);
    uint2 r;
    r.x = *reinterpret_cast<uint32_t*>(&a);
    r.y = *reinterpret_cast<uint32_t*>(&b);
    return r;
}

__device__ __forceinline__ void cpa16(uint32_t dst, const void* src) {
    asm volatile("cp.async.cg.shared.global [%0], [%1], 16;" :: "r"(dst), "l"(src));
}

__device__ __forceinline__ void ldm4(uint32_t* r, uint32_t addr) {
    asm volatile("ldmatrix.sync.aligned.m8n8.x4.shared.b16 {%0,%1,%2,%3}, [%4];"
                 : "=r"(r[0]), "=r"(r[1]), "=r"(r[2]), "=r"(r[3]) : "r"(addr));
}

__device__ __forceinline__ void ldm2(uint32_t* r, uint32_t addr) {
    asm volatile("ldmatrix.sync.aligned.m8n8.x2.shared.b16 {%0,%1}, [%2];"
                 : "=r"(r[0]), "=r"(r[1]) : "r"(addr));
}

__device__ __forceinline__ void mma16816(float* c, const uint32_t* a, uint32_t b0, uint32_t b1) {
    asm volatile(
        "mma.sync.aligned.m16n8k16.row.col.f32.f16.f16.f32 "
        "{%0,%1,%2,%3}, {%4,%5,%6,%7}, {%8,%9}, {%0,%1,%2,%3};"
        : "+f"(c[0]), "+f"(c[1]), "+f"(c[2]), "+f"(c[3])
        : "r"(a[0]), "r"(a[1]), "r"(a[2]), "r"(a[3]), "r"(b0), "r"(b1));
}

// ================= cvt_qa: qa fp32 -> fp16 (tiny) =================
__global__ void __launch_bounds__(256) cvt_qa_kernel(const float* __restrict__ qa)
{
    const int kr = blockIdx.x, tid = threadIdx.x;
    #pragma unroll
    for (int i = 0; i < 4; i++) {
        int c4 = (tid + i * 256) << 2;
        float4 f = *reinterpret_cast<const float4*>(qa + (size_t)kr * HIN + c4);
        *reinterpret_cast<uint2*>(g_qa16 + (size_t)kr * HIN + c4) = pack4h(f);
    }
}

// ================= Fused prep kernel (r12-proven: 20KB smem, K=64 LoRA chunks) ==========
// Blocks [0,256):   LoRA+x-convert: 32 x-rows each. Per K=64 chunk: LDG fp32 x ->
//                   convert in regs -> store fp16 to g_xp AND swizzled smem tile ->
//                   ldmatrix+mma against pre-converted qa. aw*tkw -> x-plane LoRA cols.
// Blocks [256,768): W->fp16 conversion (8 rows, warp-per-row) + scaling*qb cols + pad.
#define NLORA_BLK 256
// smem layout for LoRA blocks: XA0@0 XA1@4096 QB0@8192 QB1@12288 QB2@16384 (20KB)
#define PXA(s) ((uint32_t)(s) * 4096u)
#define PQB(q) (8192u + (uint32_t)(q) * 4096u)

__global__ void __launch_bounds__(256) prep_kernel(
    const float* __restrict__ x, const float* __restrict__ tkw,
    const float* __restrict__ W, const float* __restrict__ qb,
    const float* __restrict__ scaling)
{
    const int tid  = threadIdx.x;
    const int lane = tid & 31, w = tid >> 5;

    if (blockIdx.x < NLORA_BLK) {
        __shared__ __align__(128) char smem[5 * 4096];
        const uint32_t sbase = smem_u32(smem);
        const int b0 = blockIdx.x * 32;
        const int lid = lane, wid = w;
        const int mt = wid & 1, nt = wid >> 1;
        const int lr = lid & 15;
        const uint32_t lhb = (uint32_t)(lid >> 4) * 16u;

        // loader mapping (x): 2 float4 per thread per chunk
        const int xr0 = tid >> 4, xc = (tid & 15) << 2;    // rows tid>>4 and +16
        const uint32_t xd0 = (uint32_t)xr0 * 128u + (((uint32_t)xc * 2u) ^ ((uint32_t)(xr0 & 7) << 4));
        const int xr1 = xr0 + 16;
        const uint32_t xd1 = (uint32_t)xr1 * 128u + (((uint32_t)xc * 2u) ^ ((uint32_t)(xr1 & 7) << 4));
        // loader mapping (qa): 1 cpa16 per thread per chunk
        const int qr = tid >> 3, qs = tid & 7;
        const uint32_t qd = (uint32_t)qr * 128u + (((uint32_t)qs * 16u) ^ ((uint32_t)(qr & 7) << 4));

        // mma addressing (identical to validated lora_aw)
        const uint32_t arow = (uint32_t)(mt * 16 + lr);
        const uint32_t abase = arow * 128u, arx = (arow & 7u) << 4;
        const uint32_t brow = (uint32_t)(nt * 8 + (lid & 7));
        const uint32_t bbase = brow * 128u, brx = (brow & 7u) << 4;
        const uint32_t bhalf = ((uint32_t)(lid >> 3) & 1u) * 16u;

        float c[4] = {0.f, 0.f, 0.f, 0.f};
        float4 f0, f1;

        // prologue: chunk0 x in regs -> convert; qa chunks 0,1 in flight
        f0 = *reinterpret_cast<const float4*>(x + (size_t)(b0 + xr0) * HIN + xc);
        f1 = *reinterpret_cast<const float4*>(x + (size_t)(b0 + xr1) * HIN + xc);
        cpa16(sbase + PQB(0) + qd, g_qa16 + (size_t)qr * HIN + qs * 8);
        asm volatile("cp.async.commit_group;" ::: "memory");
        {
            uint2 h0 = pack4h(f0), h1 = pack4h(f1);
            *reinterpret_cast<uint2*>(smem + PXA(0) + xd0) = h0;
            *reinterpret_cast<uint2*>(smem + PXA(0) + xd1) = h1;
            *reinterpret_cast<uint2*>(g_xp + (size_t)(b0 + xr0) * KE + xc) = h0;
            *reinterpret_cast<uint2*>(g_xp + (size_t)(b0 + xr1) * KE + xc) = h1;
        }
        f0 = *reinterpret_cast<const float4*>(x + (size_t)(b0 + xr0) * HIN + 64 + xc);
        f1 = *reinterpret_cast<const float4*>(x + (size_t)(b0 + xr1) * HIN + 64 + xc);
        cpa16(sbase + PQB(1) + qd, g_qa16 + (size_t)qr * HIN + 64 + qs * 8);
        asm volatile("cp.async.commit_group;" ::: "memory");

        for (int ch = 0; ch < 64; ch++) {
            const int s = ch & 1;
            const int q = ch % 3;
            asm volatile("cp.async.wait_group 1;" ::: "memory");
            __syncthreads();
            if (ch + 1 < 64) {                       // convert x[ch+1] -> XA[1-s] + g_xp
                const int k1 = (ch + 1) * 64;
                uint2 h0 = pack4h(f0), h1 = pack4h(f1);
                *reinterpret_cast<uint2*>(smem + PXA(1 - s) + xd0) = h0;
                *reinterpret_cast<uint2*>(smem + PXA(1 - s) + xd1) = h1;
                *reinterpret_cast<uint2*>(g_xp + (size_t)(b0 + xr0) * KE + k1 + xc) = h0;
                *reinterpret_cast<uint2*>(g_xp + (size_t)(b0 + xr1) * KE + k1 + xc) = h1;
            }
            if (ch + 2 < 64) {                       // prefetch x[ch+2] regs + qa[ch+2] cpa
                const int k2 = (ch + 2) * 64;
                f0 = *reinterpret_cast<const float4*>(x + (size_t)(b0 + xr0) * HIN + k2 + xc);
                f1 = *reinterpret_cast<const float4*>(x + (size_t)(b0 + xr1) * HIN + k2 + xc);
                cpa16(sbase + PQB((ch + 2) % 3) + qd, g_qa16 + (size_t)qr * HIN + k2 + qs * 8);
            }
            asm volatile("cp.async.commit_group;" ::: "memory");

            #pragma unroll
            for (int ks = 0; ks < 4; ks++) {
                const uint32_t kb = (uint32_t)ks * 32u;
                uint32_t a[4], b[2];
                ldm4(a, sbase + PXA(s) + abase + ((kb + lhb) ^ arx));
                ldm2(b, sbase + PQB(q) + bbase + ((kb + bhalf) ^ brx));
                mma16816(c, a, b[0], b[1]);
            }
        }

        // epilogue: aw * tkw -> x-plane cols [4096,4128), fp16
        int m0r = b0 + mt * 16 + (lid >> 2);
        int col = nt * 8 + (lid & 3) * 2;
        float t0 = tkw[m0r * 4 + nt];
        float t1 = tkw[(m0r + 8) * 4 + nt];
        __half* p0 = g_xp + (size_t)m0r * KE + 4096 + col;
        __half* p1 = g_xp + (size_t)(m0r + 8) * KE + 4096 + col;
        p0[0] = __float2half(c[0] * t0);
        p0[1] = __float2half(c[1] * t0);
        p1[0] = __float2half(c[2] * t1);
        p1[1] = __float2half(c[3] * t1);
        // zero pad cols [4128,4160): 32 rows x 4 uint2
        if (tid < 128) {
            int r = tid >> 2, seg = tid & 3;
            *reinterpret_cast<uint2*>(g_xp + (size_t)(b0 + r) * KE + 4128 + seg * 8) =
                make_uint2(0u, 0u);
        }
    } else {
        // ---------------- W conversion, 8 rows, warp-per-row ----------------
        const int o0 = (blockIdx.x - NLORA_BLK) * 8;
        const int o  = o0 + w;
        const size_t rb = (size_t)o * KE;
        const float* wr = W + (size_t)o * HIN;
        #pragma unroll 8
        for (int i = 0; i < 32; i++) {
            int c4 = (i * 32 + lane) << 2;
            float4 f = *reinterpret_cast<const float4*>(wr + c4);
            *reinterpret_cast<uint2*>(g_wp + rb + c4) = pack4h(f);
        }
        if (tid < 64) {  // LoRA cols [4096,4128)
            int row = o0 + (tid >> 3), t8 = tid & 7;
            int c4 = 4096 + t8 * 4;
            int kk = t8 >> 1, rr = (t8 & 1) * 4;     // kr = kk*8 + rr..rr+3
            const float* p = qb + ((size_t)kk * HOUT + row) * 8 + rr;
            float sc = scaling[row];
            float4 f = make_float4(p[0] * sc, p[1] * sc, p[2] * sc, p[3] * sc);
            *reinterpret_cast<uint2*>(g_wp + (size_t)row * KE + c4) = pack4h(f);
        } else if (tid < 96) {  // zero pad [4128,4160)
            int row = o0 + ((tid - 64) >> 2), seg = tid & 3;
            *reinterpret_cast<uint2*>(g_wp + (size_t)row * KE + 4128 + seg * 8) =
                make_uint2(0u, 0u);
        }
    }
}

// ================= GEMM: 2 CTAs/SM, 256 threads, tile 128x128, K=64 chunks =============
// 8 warps in 4x2 grid; smem row = 128B; 3-stage ring, wait_group 1.
// Loop order (PROVEN): wait_group -> __syncthreads -> [first frags] -> issue -> compute.
// NOTE: cp.async wait_group is PER-THREAD; the __syncthreads immediately after the
// wait is what makes other threads' async copies visible. Do not reorder around it.
#define A_OFF   0
#define W_OFF   16384
#define STAGE_B 32768
#define NSTAGE  3
#define SMEM_TOTAL (NSTAGE * STAGE_B)
#define NCHUNK  65

__device__ __forceinline__ void issue_stage(uint32_t st, int ch, int m0, int n0, int tid)
{
    const int r8 = tid >> 3, sg = tid & 7;
    const size_t kofs = (size_t)ch * 64 + sg * 8;
    const uint32_t sgb = (uint32_t)sg * 16u;
    #pragma unroll
    for (int j = 0; j < 4; j++) {
        int row = r8 + 32 * j;
        uint32_t d = (uint32_t)row * 128u + (sgb ^ ((uint32_t)(row & 7) << 4));
        cpa16(st + A_OFF + d, g_xp + (size_t)(m0 + row) * KE + kofs);
    }
    #pragma unroll
    for (int j = 0; j < 4; j++) {
        int row = r8 + 32 * j;
        uint32_t d = (uint32_t)row * 128u + (sgb ^ ((uint32_t)(row & 7) << 4));
        cpa16(st + W_OFF + d, g_wp + (size_t)(n0 + row) * KE + kofs);
    }
    asm volatile("cp.async.commit_group;" ::: "memory");
}

__global__ void __launch_bounds__(256, 2) fused_gemm_kernel(float* __restrict__ out)
{
    extern __shared__ char smem[];
    const int tid = threadIdx.x;
    const int wid = tid >> 5, lid = tid & 31;
    const int wr = wid >> 1, wc = wid & 1;
    const int n0 = blockIdx.x * 128;
    const int m0 = blockIdx.y * 128;
    const uint32_t sbase = smem_u32(smem);
    const int lr = lid & 15;
    const uint32_t lhb = (uint32_t)(lid >> 4) * 16u;

    uint32_t abase[2], arx[2], bbase[4], brx[4];
    #pragma unroll
    for (int t = 0; t < 2; t++) {
        uint32_t row = (uint32_t)(wr * 32 + t * 16 + lr);
        abase[t] = row * 128u; arx[t] = (row & 7u) << 4;
    }
    #pragma unroll
    for (int g = 0; g < 4; g++) {
        uint32_t row = (uint32_t)(wc * 64 + g * 16 + lr);
        bbase[g] = row * 128u; brx[g] = (row & 7u) << 4;
    }

    float acc[2][8][4];
    #pragma unroll
    for (int t = 0; t < 2; t++)
        #pragma unroll
        for (int j = 0; j < 8; j++)
            #pragma unroll
            for (int e = 0; e < 4; e++) acc[t][j][e] = 0.f;

    issue_stage(sbase + 0 * STAGE_B, 0, m0, n0, tid);
    issue_stage(sbase + 1 * STAGE_B, 1, m0, n0, tid);

    int sidx = 0;
    for (int ch = 0; ch < NCHUNK; ch++) {
        const uint32_t st = sbase + sidx * STAGE_B;
        const uint32_t sa = st + A_OFF, sw = st + W_OFF;

        asm volatile("cp.async.wait_group 1;" ::: "memory");
        __syncthreads();

        // hoist first k-step fragments: LDSM latency overlaps the LDGSTS issue below
        uint32_t ah0[2][4];
        uint32_t bfirst[4];
        ldm4(ah0[0], sa + abase[0] + (lhb ^ arx[0]));
        ldm4(ah0[1], sa + abase[1] + (lhb ^ arx[1]));
        ldm4(bfirst, sw + bbase[0] + (lhb ^ brx[0]));

        if (ch + 2 < NCHUNK) {
            int ps = sidx + 2; if (ps >= NSTAGE) ps -= NSTAGE;
            issue_stage(sbase + ps * STAGE_B, ch + 2, m0, n0, tid);
        } else {
            asm volatile("cp.async.commit_group;" ::: "memory");  // keep group count in step
        }

        #pragma unroll
        for (int ks = 0; ks < 4; ks++) {
            const uint32_t chb = (uint32_t)ks * 32u + lhb;
            uint32_t ah[2][4];
            if (ks == 0) {
                #pragma unroll
                for (int e = 0; e < 4; e++) { ah[0][e] = ah0[0][e]; ah[1][e] = ah0[1][e]; }
            } else {
                ldm4(ah[0], sa + abase[0] + (chb ^ arx[0]));
                ldm4(ah[1], sa + abase[1] + (chb ^ arx[1]));
            }

            uint32_t bfrag[2][4];
            if (ks == 0) {
                #pragma unroll
                for (int e = 0; e < 4; e++) bfrag[0][e] = bfirst[e];
            } else {
                ldm4(bfrag[0], sw + bbase[0] + (chb ^ brx[0]));
            }
            #pragma unroll
            for (int g = 0; g < 4; g++) {
                const int cur = g & 1;
                if (g < 3)
                    ldm4(bfrag[cur ^ 1], sw + bbase[g + 1] + (chb ^ brx[g + 1]));
                #pragma unroll
                for (int t = 0; t < 2; t++) {
                    #pragma unroll
                    for (int j2 = 0; j2 < 2; j2++)
                        mma16816(acc[t][g * 2 + j2], ah[t],
                                 bfrag[cur][j2], bfrag[cur][j2 + 2]);
                }
            }
        }
        if (++sidx >= NSTAGE) sidx = 0;
    }

    #pragma unroll
    for (int t = 0; t < 2; t++) {
        int mr = m0 + wr * 32 + t * 16 + (lid >> 2);
        #pragma unroll
        for (int j = 0; j < 8; j++) {
            int col = n0 + wc * 64 + j * 8 + (lid & 3) * 2;
            *reinterpret_cast<float2*>(out + (size_t)mr * HOUT + col) =
                make_float2(acc[t][j][0], acc[t][j][1]);
            *reinterpret_cast<float2*>(out + (size_t)(mr + 8) * HOUT + col) =
                make_float2(acc[t][j][2], acc[t][j][3]);
        }
    }
}

// ================= launch =================
extern "C" void kernel_launch(void* const* d_in, const int* in_sizes, int n_in,
                              void* d_out, int out_size) {
    const float* x       = (const float*)d_in[0];
    const float* tkw     = (const float*)d_in[1];
    const float* W       = (const float*)d_in[2];
    const float* qa      = (const float*)d_in[3];
    const float* qb      = (const float*)d_in[4];
    const float* scaling = (const float*)d_in[5];
    float* out = (float*)d_out;

    cvt_qa_kernel<<<32, 256>>>(qa);
    prep_kernel<<<NLORA_BLK + HOUT / 8, 256>>>(x, tkw, W, qb, scaling);

    cudaFuncSetAttribute(fused_gemm_kernel,
                         cudaFuncAttributeMaxDynamicSharedMemorySize, SMEM_TOTAL);
    dim3 grid(HOUT / 128, B_DIM / 128);
    fused_gemm_kernel<<<grid, 256, SMEM_TOTAL>>>(out);
}

// round 16
// speedup vs baseline: 1.2827x; 1.0218x over previous
#include <cuda_runtime.h>
#include <cuda_fp16.h>
#include <cstdint>
#include <cstddef>

#define B_DIM 8192
#define HIN   4096
#define HOUT  4096
#define KE    4160          // 4096 + 32 LoRA + 32 zero pad = 65 chunks of K=64

// ---------------- device scratch ----------------
__device__ __align__(16) __half g_xp[(size_t)B_DIM * KE];
__device__ __align__(16) __half g_wp[(size_t)HOUT * KE];

// ---------------- helpers ----------------
__device__ __forceinline__ uint32_t smem_u32(const void* p) {
    uint32_t a;
    asm("{ .reg .u64 t; cvta.to.shared.u64 t, %1; cvt.u32.u64 %0, t; }" : "=r"(a) : "l"(p));
    return a;
}

__device__ __forceinline__ uint2 pack4h(float4 f) {
    __half2 a = __floats2half2_rn(f.x, f.y);
    __half2 b = __floats2half2_rn(f.z, f.w);
    uint2 r;
    r.x = *reinterpret_cast<uint32_t*>(&a);
    r.y = *reinterpret_cast<uint32_t*>(&b);
    return r;
}

__device__ __forceinline__ void cpa16(uint32_t dst, const void* src) {
    asm volatile("cp.async.cg.shared.global [%0], [%1], 16;" :: "r"(dst), "l"(src));
}

__device__ __forceinline__ void ldm4(uint32_t* r, uint32_t addr) {
    asm volatile("ldmatrix.sync.aligned.m8n8.x4.shared.b16 {%0,%1,%2,%3}, [%4];"
                 : "=r"(r[0]), "=r"(r[1]), "=r"(r[2]), "=r"(r[3]) : "r"(addr));
}

__device__ __forceinline__ void ldm2(uint32_t* r, uint32_t addr) {
    asm volatile("ldmatrix.sync.aligned.m8n8.x2.shared.b16 {%0,%1}, [%2];"
                 : "=r"(r[0]), "=r"(r[1]) : "r"(addr));
}

__device__ __forceinline__ void mma16816(float* c, const uint32_t* a, uint32_t b0, uint32_t b1) {
    asm volatile(
        "mma.sync.aligned.m16n8k16.row.col.f32.f16.f16.f32 "
        "{%0,%1,%2,%3}, {%4,%5,%6,%7}, {%8,%9}, {%0,%1,%2,%3};"
        : "+f"(c[0]), "+f"(c[1]), "+f"(c[2]), "+f"(c[3])
        : "r"(a[0]), "r"(a[1]), "r"(a[2]), "r"(a[3]), "r"(b0), "r"(b1));
}

// ================= Fused prep kernel =================
// Blocks [0,256):   LoRA+x-convert, 32 x-rows each. Per K=64 chunk: LDG fp32 x AND qa ->
//                   convert in regs -> x to g_xp + smem XA, qa to smem QB ->
//                   ldmatrix+mma. Pure double-buffer, no cp.async.
// Blocks [256,768): W->fp16 conversion (8 rows, warp-per-row) + scaling*qb cols + pad.
#define NLORA_BLK 256
// LoRA smem: XA0@0 XA1@4096 QB0@8192 QB1@12288 (16KB)
#define PXA(s) ((uint32_t)(s) * 4096u)
#define PQB(s) (8192u + (uint32_t)(s) * 4096u)

__global__ void __launch_bounds__(256) prep_kernel(
    const float* __restrict__ x, const float* __restrict__ tkw,
    const float* __restrict__ qa,
    const float* __restrict__ W, const float* __restrict__ qb,
    const float* __restrict__ scaling)
{
    const int tid  = threadIdx.x;
    const int lane = tid & 31, w = tid >> 5;

    if (blockIdx.x < NLORA_BLK) {
        __shared__ __align__(128) char smem[4 * 4096];
        const uint32_t sbase = smem_u32(smem);
        const int b0 = blockIdx.x * 32;
        const int lid = lane, wid = w;
        const int mt = wid & 1, nt = wid >> 1;
        const int lr = lid & 15;
        const uint32_t lhb = (uint32_t)(lid >> 4) * 16u;

        // tile loader mapping (both x and qa are 32 rows x 64 cols per chunk):
        // thread -> rows (tid>>4, +16), col (tid&15)*4
        const int tr0 = tid >> 4, tc = (tid & 15) << 2;
        const int tr1 = tr0 + 16;
        const uint32_t td0 = (uint32_t)tr0 * 128u + (((uint32_t)tc * 2u) ^ ((uint32_t)(tr0 & 7) << 4));
        const uint32_t td1 = (uint32_t)tr1 * 128u + (((uint32_t)tc * 2u) ^ ((uint32_t)(tr1 & 7) << 4));

        const float* xb0 = x + (size_t)(b0 + tr0) * HIN;
        const float* xb1 = x + (size_t)(b0 + tr1) * HIN;
        const float* qb0p = qa + (size_t)tr0 * HIN;   // qa row = kr index
        const float* qb1p = qa + (size_t)tr1 * HIN;

        // mma addressing (validated lora_aw layout)
        const uint32_t arow = (uint32_t)(mt * 16 + lr);
        const uint32_t abase = arow * 128u, arx = (arow & 7u) << 4;
        const uint32_t brow = (uint32_t)(nt * 8 + (lid & 7));
        const uint32_t bbase = brow * 128u, brx = (brow & 7u) << 4;
        const uint32_t bhalf = ((uint32_t)(lid >> 3) & 1u) * 16u;

        float c[4] = {0.f, 0.f, 0.f, 0.f};
        float4 fx0, fx1, fq0, fq1;   // prefetch regs for next chunk

        // prologue: chunk0 -> regs -> convert into buffers [0]; chunk1 -> regs
        fx0 = *reinterpret_cast<const float4*>(xb0 + tc);
        fx1 = *reinterpret_cast<const float4*>(xb1 + tc);
        fq0 = *reinterpret_cast<const float4*>(qb0p + tc);
        fq1 = *reinterpret_cast<const float4*>(qb1p + tc);
        {
            uint2 hx0 = pack4h(fx0), hx1 = pack4h(fx1);
            uint2 hq0 = pack4h(fq0), hq1 = pack4h(fq1);
            *reinterpret_cast<uint2*>(smem + PXA(0) + td0) = hx0;
            *reinterpret_cast<uint2*>(smem + PXA(0) + td1) = hx1;
            *reinterpret_cast<uint2*>(smem + PQB(0) + td0) = hq0;
            *reinterpret_cast<uint2*>(smem + PQB(0) + td1) = hq1;
            *reinterpret_cast<uint2*>(g_xp + (size_t)(b0 + tr0) * KE + tc) = hx0;
            *reinterpret_cast<uint2*>(g_xp + (size_t)(b0 + tr1) * KE + tc) = hx1;
        }
        fx0 = *reinterpret_cast<const float4*>(xb0 + 64 + tc);
        fx1 = *reinterpret_cast<const float4*>(xb1 + 64 + tc);
        fq0 = *reinterpret_cast<const float4*>(qb0p + 64 + tc);
        fq1 = *reinterpret_cast<const float4*>(qb1p + 64 + tc);

        for (int ch = 0; ch < 64; ch++) {
            const int s = ch & 1;
            __syncthreads();   // buffer [s] writes (prev iter / prologue) visible;
                               // prior reads of [1-s] complete before overwrite
            if (ch + 1 < 64) {                       // convert chunk ch+1 -> buffers [1-s]
                const int k1 = (ch + 1) * 64;
                uint2 hx0 = pack4h(fx0), hx1 = pack4h(fx1);
                uint2 hq0 = pack4h(fq0), hq1 = pack4h(fq1);
                *reinterpret_cast<uint2*>(smem + PXA(1 - s) + td0) = hx0;
                *reinterpret_cast<uint2*>(smem + PXA(1 - s) + td1) = hx1;
                *reinterpret_cast<uint2*>(smem + PQB(1 - s) + td0) = hq0;
                *reinterpret_cast<uint2*>(smem + PQB(1 - s) + td1) = hq1;
                *reinterpret_cast<uint2*>(g_xp + (size_t)(b0 + tr0) * KE + k1 + tc) = hx0;
                *reinterpret_cast<uint2*>(g_xp + (size_t)(b0 + tr1) * KE + k1 + tc) = hx1;
            }
            if (ch + 2 < 64) {                       // prefetch chunk ch+2 -> regs
                const int k2 = (ch + 2) * 64;
                fx0 = *reinterpret_cast<const float4*>(xb0 + k2 + tc);
                fx1 = *reinterpret_cast<const float4*>(xb1 + k2 + tc);
                fq0 = *reinterpret_cast<const float4*>(qb0p + k2 + tc);
                fq1 = *reinterpret_cast<const float4*>(qb1p + k2 + tc);
            }

            #pragma unroll
            for (int ks = 0; ks < 4; ks++) {
                const uint32_t kb = (uint32_t)ks * 32u;
                uint32_t a[4], b[2];
                ldm4(a, sbase + PXA(s) + abase + ((kb + lhb) ^ arx));
                ldm2(b, sbase + PQB(s) + bbase + ((kb + bhalf) ^ brx));
                mma16816(c, a, b[0], b[1]);
            }
        }

        // epilogue: aw * tkw -> x-plane cols [4096,4128), fp16
        int m0r = b0 + mt * 16 + (lid >> 2);
        int col = nt * 8 + (lid & 3) * 2;
        float t0 = tkw[m0r * 4 + nt];
        float t1 = tkw[(m0r + 8) * 4 + nt];
        __half* p0 = g_xp + (size_t)m0r * KE + 4096 + col;
        __half* p1 = g_xp + (size_t)(m0r + 8) * KE + 4096 + col;
        p0[0] = __float2half(c[0] * t0);
        p0[1] = __float2half(c[1] * t0);
        p1[0] = __float2half(c[2] * t1);
        p1[1] = __float2half(c[3] * t1);
        // zero pad cols [4128,4160): 32 rows x 4 uint2
        if (tid < 128) {
            int r = tid >> 2, seg = tid & 3;
            *reinterpret_cast<uint2*>(g_xp + (size_t)(b0 + r) * KE + 4128 + seg * 8) =
                make_uint2(0u, 0u);
        }
    } else {
        // ---------------- W conversion, 8 rows, warp-per-row ----------------
        const int o0 = (blockIdx.x - NLORA_BLK) * 8;
        const int o  = o0 + w;
        const size_t rb = (size_t)o * KE;
        const float* wr = W + (size_t)o * HIN;
        #pragma unroll 8
        for (int i = 0; i < 32; i++) {
            int c4 = (i * 32 + lane) << 2;
            float4 f = *reinterpret_cast<const float4*>(wr + c4);
            *reinterpret_cast<uint2*>(g_wp + rb + c4) = pack4h(f);
        }
        if (tid < 64) {  // LoRA cols [4096,4128)
            int row = o0 + (tid >> 3), t8 = tid & 7;
            int c4 = 4096 + t8 * 4;
            int kk = t8 >> 1, rr = (t8 & 1) * 4;     // kr = kk*8 + rr..rr+3
            const float* p = qb + ((size_t)kk * HOUT + row) * 8 + rr;
            float sc = scaling[row];
            float4 f = make_float4(p[0] * sc, p[1] * sc, p[2] * sc, p[3] * sc);
            *reinterpret_cast<uint2*>(g_wp + (size_t)row * KE + c4) = pack4h(f);
        } else if (tid < 96) {  // zero pad [4128,4160)
            int row = o0 + ((tid - 64) >> 2), seg = tid & 3;
            *reinterpret_cast<uint2*>(g_wp + (size_t)row * KE + 4128 + seg * 8) =
                make_uint2(0u, 0u);
        }
    }
}

// ================= GEMM: 2 CTAs/SM, 256 threads, tile 128x128, K=64 chunks =============
// EXACT r12-proven form (759.8 us). 8 warps in 4x2 grid; smem row = 128B;
// 3-stage ring, wait_group 1. Loop order: wait -> __syncthreads -> issue -> compute.
// NOTE: cp.async wait_group is PER-THREAD; the __syncthreads immediately after the
// wait is what makes other threads' async copies visible. Do not reorder.
#define A_OFF   0
#define W_OFF   16384
#define STAGE_B 32768
#define NSTAGE  3
#define SMEM_TOTAL (NSTAGE * STAGE_B)
#define NCHUNK  65

__device__ __forceinline__ void issue_stage(uint32_t st, int ch, int m0, int n0, int tid)
{
    const int r8 = tid >> 3, sg = tid & 7;
    const size_t kofs = (size_t)ch * 64 + sg * 8;
    const uint32_t sgb = (uint32_t)sg * 16u;
    #pragma unroll
    for (int j = 0; j < 4; j++) {
        int row = r8 + 32 * j;
        uint32_t d = (uint32_t)row * 128u + (sgb ^ ((uint32_t)(row & 7) << 4));
        cpa16(st + A_OFF + d, g_xp + (size_t)(m0 + row) * KE + kofs);
    }
    #pragma unroll
    for (int j = 0; j < 4; j++) {
        int row = r8 + 32 * j;
        uint32_t d = (uint32_t)row * 128u + (sgb ^ ((uint32_t)(row & 7) << 4));
        cpa16(st + W_OFF + d, g_wp + (size_t)(n0 + row) * KE + kofs);
    }
    asm volatile("cp.async.commit_group;" ::: "memory");
}

__global__ void __launch_bounds__(256, 2) fused_gemm_kernel(float* __restrict__ out)
{
    extern __shared__ char smem[];
    const int tid = threadIdx.x;
    const int wid = tid >> 5, lid = tid & 31;
    const int wr = wid >> 1, wc = wid & 1;
    const int n0 = blockIdx.x * 128;
    const int m0 = blockIdx.y * 128;
    const uint32_t sbase = smem_u32(smem);
    const int lr = lid & 15;
    const uint32_t lhb = (uint32_t)(lid >> 4) * 16u;

    uint32_t abase[2], arx[2], bbase[4], brx[4];
    #pragma unroll
    for (int t = 0; t < 2; t++) {
        uint32_t row = (uint32_t)(wr * 32 + t * 16 + lr);
        abase[t] = row * 128u; arx[t] = (row & 7u) << 4;
    }
    #pragma unroll
    for (int g = 0; g < 4; g++) {
        uint32_t row = (uint32_t)(wc * 64 + g * 16 + lr);
        bbase[g] = row * 128u; brx[g] = (row & 7u) << 4;
    }

    float acc[2][8][4];
    #pragma unroll
    for (int t = 0; t < 2; t++)
        #pragma unroll
        for (int j = 0; j < 8; j++)
            #pragma unroll
            for (int e = 0; e < 4; e++) acc[t][j][e] = 0.f;

    issue_stage(sbase + 0 * STAGE_B, 0, m0, n0, tid);
    issue_stage(sbase + 1 * STAGE_B, 1, m0, n0, tid);

    int sidx = 0;
    for (int ch = 0; ch < NCHUNK; ch++) {
        const uint32_t st = sbase + sidx * STAGE_B;
        const uint32_t sa = st + A_OFF, sw = st + W_OFF;

        asm volatile("cp.async.wait_group 1;" ::: "memory");
        __syncthreads();
        if (ch + 2 < NCHUNK) {
            int ps = sidx + 2; if (ps >= NSTAGE) ps -= NSTAGE;
            issue_stage(sbase + ps * STAGE_B, ch + 2, m0, n0, tid);
        } else {
            asm volatile("cp.async.commit_group;" ::: "memory");  // keep group count in step
        }

        #pragma unroll
        for (int ks = 0; ks < 4; ks++) {
            const uint32_t chb = (uint32_t)ks * 32u + lhb;
            uint32_t ah[2][4];
            ldm4(ah[0], sa + abase[0] + (chb ^ arx[0]));
            ldm4(ah[1], sa + abase[1] + (chb ^ arx[1]));

            uint32_t bfrag[2][4];
            ldm4(bfrag[0], sw + bbase[0] + (chb ^ brx[0]));
            #pragma unroll
            for (int g = 0; g < 4; g++) {
                const int cur = g & 1;
                if (g < 3)
                    ldm4(bfrag[cur ^ 1], sw + bbase[g + 1] + (chb ^ brx[g + 1]));
                #pragma unroll
                for (int t = 0; t < 2; t++) {
                    #pragma unroll
                    for (int j2 = 0; j2 < 2; j2++)
                        mma16816(acc[t][g * 2 + j2], ah[t],
                                 bfrag[cur][j2], bfrag[cur][j2 + 2]);
                }
            }
        }
        if (++sidx >= NSTAGE) sidx = 0;
    }

    #pragma unroll
    for (int t = 0; t < 2; t++) {
        int mr = m0 + wr * 32 + t * 16 + (lid >> 2);
        #pragma unroll
        for (int j = 0; j < 8; j++) {
            int col = n0 + wc * 64 + j * 8 + (lid & 3) * 2;
            *reinterpret_cast<float2*>(out + (size_t)mr * HOUT + col) =
                make_float2(acc[t][j][0], acc[t][j][1]);
            *reinterpret_cast<float2*>(out + (size_t)(mr + 8) * HOUT + col) =
                make_float2(acc[t][j][2], acc[t][j][3]);
        }
    }
}

// ================= launch =================
extern "C" void kernel_launch(void* const* d_in, const int* in_sizes, int n_in,
                              void* d_out, int out_size) {
    const float* x       = (const float*)d_in[0];
    const float* tkw     = (const float*)d_in[1];
    const float* W       = (const float*)d_in[2];
    const float* qa      = (const float*)d_in[3];
    const float* qb      = (const float*)d_in[4];
    const float* scaling = (const float*)d_in[5];
    float* out = (float*)d_out;

    prep_kernel<<<NLORA_BLK + HOUT / 8, 256>>>(x, tkw, qa, W, qb, scaling);

    cudaFuncSetAttribute(fused_gemm_kernel,
                         cudaFuncAttributeMaxDynamicSharedMemorySize, SMEM_TOTAL);
    dim3 grid(HOUT / 128, B_DIM / 128);
    fused_gemm_kernel<<<grid, 256, SMEM_TOTAL>>>(out);
}